// round 9
// baseline (speedup 1.0000x reference)
#include <cuda_runtime.h>
#include <cstdint>

#define NN 4
#define PP 128
#define HH 64
#define UU 64
#define BB 15
#define FAVG 49.0f
#define NPG 64   // p-groups for colsum partials (2 p's each)

// ---------------- device scratch ----------------
__device__ float g_rows[NN*HH*PP];         // sum_q x / npart   [n][h][p]
__device__ float g_diag[NN*HH*PP];         // x[p,p]            [n][h][p]
__device__ float g_cpart[NPG*NN*PP*HH];    // partial colsums   [pg][n][q][h]  (8MB)
__device__ float g_Fq[NN*PP*UU];           // q-field (includes bias)
__device__ float g_Fp[NN*PP*UU];           // p-field (includes scalar terms)
__device__ float g_Fd[NN*PP*UU];           // diag field (includes diag_bias + scalar terms)

// ---------------- f32x2 helpers ----------------
#define FMA2(d, a, b) asm("fma.rn.f32x2 %0, %1, %2, %0;" : "+l"(d) : "l"(a), "l"(b))
#define PK2(d, f) do { unsigned int _t = __float_as_uint(f); \
    asm("mov.b64 %0, {%1, %1};" : "=l"(d) : "r"(_t)); } while (0)
#define UPK2(lo, hi, v) asm("mov.b64 {%0, %1}, %2;" : "=f"(lo), "=f"(hi) : "l"(v))

// ---------------- pass 1 (fused): single x read -> rows, diag, colsum partials ----------------
// grid (NPG, NN), 256 threads. Block covers p in [p0, p0+2).
__global__ void __launch_bounds__(256)
fuse_kernel(const float* __restrict__ x, const float* __restrict__ npart) {
    const int pg = blockIdx.x;         // p-group (2 p's)
    const int n  = blockIdx.y;
    const int p0 = pg * 2;
    const int t  = threadIdx.x;
    const int h4 = t & 15;             // float4 h-group
    const int qg = t >> 4;             // 0..15

    __shared__ float4 spart[16][2][16];   // [qg][p][h4] rowsum partials (8KB)

    const float4* x4 = (const float4*)x;
    const float inv = 1.0f / npart[n];

    float4 col[8];
    #pragma unroll
    for (int j = 0; j < 8; ++j) col[j] = make_float4(0.f, 0.f, 0.f, 0.f);

    #pragma unroll
    for (int p = 0; p < 2; ++p) {
        float4 rp = make_float4(0.f, 0.f, 0.f, 0.f);
        const size_t base = ((size_t)(n * PP + p0 + p)) * PP * 16;  // float4 units
        #pragma unroll
        for (int j = 0; j < 8; ++j) {
            const int q = qg + j * 16;
            const float4 v = x4[base + q * 16 + h4];
            col[j].x += v.x; col[j].y += v.y; col[j].z += v.z; col[j].w += v.w;
            rp.x += v.x; rp.y += v.y; rp.z += v.z; rp.w += v.w;
        }
        spart[qg][p][h4] = rp;
    }

    // colsum partials -> g_cpart[pg][n][q][h]
    {
        float4* cp = (float4*)g_cpart + ((size_t)(pg * NN + n)) * PP * 16;
        #pragma unroll
        for (int j = 0; j < 8; ++j)
            cp[(qg + j * 16) * 16 + h4] = col[j];
    }
    __syncthreads();

    // rowsum finish + diag: threads 0..31 -> (p = t>>4, h4 = t&15)
    if (t < 32) {
        const int p   = t >> 4;
        const int hh4 = t & 15;
        float4 r = spart[0][p][hh4];
        #pragma unroll
        for (int g = 1; g < 16; ++g) {
            const float4 v = spart[g][p][hh4];
            r.x += v.x; r.y += v.y; r.z += v.z; r.w += v.w;
        }
        const int P = p0 + p;
        const int gb = (n * HH + hh4 * 4) * PP + P;
        g_rows[gb + 0*PP] = r.x * inv;
        g_rows[gb + 1*PP] = r.y * inv;
        g_rows[gb + 2*PP] = r.z * inv;
        g_rows[gb + 3*PP] = r.w * inv;
        const float4 d = x4[(((size_t)(n * PP + P)) * PP + P) * 16 + hh4];
        g_diag[gb + 0*PP] = d.x;
        g_diag[gb + 1*PP] = d.y;
        g_diag[gb + 2*PP] = d.z;
        g_diag[gb + 3*PP] = d.w;
    }
}

// ---------------- pass 2 (fused): scalars + coefficients + field GEMMs ----------------
__global__ void __launch_bounds__(256)
pro_kernel(const float* __restrict__ npart,
           const float* __restrict__ alpha0,
           const float* __restrict__ c00,
           const float* __restrict__ c01,
           const float* __restrict__ c10,
           const float* __restrict__ c11,
           const float* __restrict__ bias,
           const float* __restrict__ dbias) {
    const int n  = blockIdx.y;
    const int i0 = blockIdx.x * 4;
    const int tid = threadIdx.x;

    __shared__ float sRR[HH * UU];     // c10*c11  [h][u]
    __shared__ float sD[HH][4], sC[HH][4], sR[HH][4];
    __shared__ float sSD[HH], sSA[HH];
    __shared__ float sM[HH][10];
    __shared__ float sA[HH][16];       // c00 rows (15 used)

    const float np  = npart[n];
    const float inv = 1.0f / np;

    #pragma unroll
    for (int it = 0; it < 16; ++it) {
        const int idx = tid + it * 256;
        sRR[idx] = c10[idx] * c11[idx];
    }
    // sD/sR slices
    {
        const int hh = tid >> 2;
        const int ii = tid & 3;
        const int gi = (n * HH + hh) * PP + i0 + ii;
        sD[hh][ii] = g_diag[gi];
        sR[hh][ii] = g_rows[gi];
    }
    // colsum: fold NPG partials; thread (hh = tid&63, ii = tid>>6)
    {
        const int hh = tid & 63;
        const int ii = tid >> 6;
        const float* cp = g_cpart + ((size_t)n * PP + i0 + ii) * HH + hh;
        float s = 0.0f;
        #pragma unroll 16
        for (int g = 0; g < NPG; ++g)
            s += cp[(size_t)g * (NN * PP * HH)];
        sC[hh][ii] = s * inv;
    }
    // sd/sa: warp w reduces h = w*8..w*8+7
    {
        const int w = tid >> 5, lane = tid & 31;
        #pragma unroll
        for (int j = 0; j < 8; ++j) {
            const int h = w * 8 + j;
            const int base = (n * HH + h) * PP;
            float d = g_diag[base + lane] + g_diag[base + lane + 32]
                    + g_diag[base + lane + 64] + g_diag[base + lane + 96];
            float r = g_rows[base + lane] + g_rows[base + lane + 32]
                    + g_rows[base + lane + 64] + g_rows[base + lane + 96];
            #pragma unroll
            for (int o = 16; o > 0; o >>= 1) {
                d += __shfl_down_sync(0xffffffffu, d, o);
                r += __shfl_down_sync(0xffffffffu, r, o);
            }
            if (lane == 0) { sSD[h] = d * inv; sSA[h] = r * inv; }
        }
    }
    {
        const float ratio = np / FAVG;
        for (int idx = tid; idx < HH * 10; idx += 256)
            sM[idx / 10][idx % 10] = powf(ratio, alpha0[idx]);
    }
    for (int idx = tid; idx < HH * BB; idx += 256)
        sA[idx / BB][idx % BB] = c00[idx];
    __syncthreads();

    const int u  = tid & 63;
    const int ii = tid >> 6;

    float cb[BB];
    #pragma unroll
    for (int b = 2; b < BB; ++b) cb[b] = c01[b * UU + u];

    float aq = 0.0f, ap = 0.0f, ad = 0.0f, vp = 0.0f, vd = 0.0f;

    #pragma unroll 4
    for (int h = 0; h < HH; ++h) {
        const float r = sRR[h * UU + u];
        const float* a = sA[h];
        const float* m = sM[h];
        const float d  = sD[h][ii];
        const float cl = sC[h][ii];
        const float rw = sR[h][ii];
        aq += (a[2]  * cb[2]  * r)        * d
            + (a[5]  * cb[5]  * r * m[0]) * cl
            + (a[6]  * cb[6]  * r * m[1]) * rw;
        ap += (a[3]  * cb[3]  * r)        * d
            + (a[8]  * cb[8]  * r * m[3]) * cl
            + (a[9]  * cb[9]  * r * m[4]) * rw;
        ad += (a[4]  * cb[4]  * r)        * d
            + (a[12] * cb[12] * r * m[7]) * cl
            + (a[11] * cb[11] * r * m[6]) * rw;
        vp += (a[7]  * cb[7]  * r * m[2]) * sSD[h]
            + (a[13] * cb[13] * r * m[8]) * sSA[h];
        vd += (a[10] * cb[10] * r * m[5]) * sSD[h]
            + (a[14] * cb[14] * r * m[9]) * sSA[h];
    }

    const int i = i0 + ii;
    g_Fq[(n * PP + i) * UU + u] = aq + bias[u];
    g_Fp[(n * PP + i) * UU + u] = ap + vp;
    g_Fd[(n * PP + i) * UU + u] = ad + vd + dbias[u];
}

// ---------------- main: dual skinny GEMM with packed f32x2 FMAs ----------------
constexpr int SMEM_FLOATS = 2 * 64 * 128 + 2 * 64 * 64 + 128;

__global__ void __launch_bounds__(256, 2)
main_kernel(const float* __restrict__ x,
            const unsigned int* __restrict__ mask,
            const float* __restrict__ c00,
            const float* __restrict__ c01,
            const float* __restrict__ c10,
            const float* __restrict__ c11,
            float* __restrict__ out) {
    extern __shared__ float sm[];
    float* sXd = sm;                         // [k=64][q=128] XOR-swizzled
    float* sXt = sXd + 64 * 128;             // [k=64][q=128] XOR-swizzled
    float* sC0 = sXt + 64 * 128;             // [k=64][u=64]
    float* sC1 = sC0 + 64 * 64;
    float* sFp = sC1 + 64 * 64;              // [64]
    float* sFd = sFp + 64;                   // [64]

    const int p = blockIdx.x;
    const int n = blockIdx.y;
    const int tid = threadIdx.x;

    // direct tile: x[n,p,q,h] -> sXd[h][swz(q)]
    const float4* xrow4 = (const float4*)(x + ((size_t)(n * PP + p)) * PP * HH);
    #pragma unroll
    for (int it = 0; it < 8; ++it) {
        const int idx4 = tid + it * 256;           // [q][h/4]
        const float4 v = xrow4[idx4];
        const int q  = idx4 >> 4;
        const int h0 = (idx4 & 15) << 2;
        const int qs = q ^ ((idx4 & 7) << 3);
        sXd[(h0 + 0) * 128 + qs] = v.x;
        sXd[(h0 + 1) * 128 + qs] = v.y;
        sXd[(h0 + 2) * 128 + qs] = v.z;
        sXd[(h0 + 3) * 128 + qs] = v.w;
    }
    // transposed tile: x[n,r,p,h] -> sXt[h][swz(r)]
    {
        const int h0 = (tid & 15) << 2;
        const int sw = (tid & 7) << 3;
        #pragma unroll
        for (int it = 0; it < 8; ++it) {
            const int r = (tid >> 4) + it * 16;
            const float4 v = *(const float4*)(x + (((size_t)(n * PP + r)) * PP + p) * HH + h0);
            const int rs = r ^ sw;
            sXt[(h0 + 0) * 128 + rs] = v.x;
            sXt[(h0 + 1) * 128 + rs] = v.y;
            sXt[(h0 + 2) * 128 + rs] = v.z;
            sXt[(h0 + 3) * 128 + rs] = v.w;
        }
    }
    // compute C0/C1 in-block from raw coefficients
    #pragma unroll
    for (int it = 0; it < 16; ++it) {
        const int idx = tid + it * 256;      // 0..4095 = h*64+u
        const int h = idx >> 6;
        const int uu = idx & 63;
        const float r = c10[idx] * c11[idx];
        sC0[idx] = c00[h * BB + 0] * c01[uu] * r;
        sC1[idx] = c00[h * BB + 1] * c01[UU + uu] * r;
    }
    if (tid < 64) {
        sFp[tid] = g_Fp[(n * PP + p) * UU + tid];
        sFd[tid] = g_Fd[(n * PP + p) * UU + tid];
    }
    __syncthreads();

    const int tx = tid & 15;
    const int ty = tid >> 4;
    const int u0 = tx << 2;
    const int q0 = ty << 3;

    unsigned long long acc[4][4];
    #pragma unroll
    for (int i = 0; i < 4; ++i)
        #pragma unroll
        for (int j = 0; j < 4; ++j) acc[i][j] = 0ULL;

    #pragma unroll 4
    for (int k = 0; k < 64; ++k) {
        const float4 b0 = *(const float4*)(sC0 + k * 64 + u0);
        const float4 b1 = *(const float4*)(sC1 + k * 64 + u0);
        unsigned long long bb0[4], bb1[4];
        PK2(bb0[0], b0.x); PK2(bb0[1], b0.y); PK2(bb0[2], b0.z); PK2(bb0[3], b0.w);
        PK2(bb1[0], b1.x); PK2(bb1[1], b1.y); PK2(bb1[2], b1.z); PK2(bb1[3], b1.w);
        const int kq = k * 128 + (q0 ^ (((k >> 2) & 7) << 3));
        const ulonglong2 a01 = *(const ulonglong2*)(sXd + kq);
        const ulonglong2 a23 = *(const ulonglong2*)(sXd + kq + 4);
        const ulonglong2 t01 = *(const ulonglong2*)(sXt + kq);
        const ulonglong2 t23 = *(const ulonglong2*)(sXt + kq + 4);
        const unsigned long long av[4] = {a01.x, a01.y, a23.x, a23.y};
        const unsigned long long tv[4] = {t01.x, t01.y, t23.x, t23.y};
        #pragma unroll
        for (int qp = 0; qp < 4; ++qp)
            #pragma unroll
            for (int j = 0; j < 4; ++j) {
                FMA2(acc[qp][j], av[qp], bb0[j]);
                FMA2(acc[qp][j], tv[qp], bb1[j]);
            }
    }

    // epilogue
    const float4 fp4 = *(const float4*)(sFp + u0);
    const float4 fd4 = *(const float4*)(sFd + u0);
    const unsigned int* em = mask + (size_t)(n * PP + p) * PP;
    #pragma unroll
    for (int qp = 0; qp < 4; ++qp) {
        float lo[4], hi[4];
        #pragma unroll
        for (int j = 0; j < 4; ++j) UPK2(lo[j], hi[j], acc[qp][j]);
        #pragma unroll
        for (int half = 0; half < 2; ++half) {
            const int q = q0 + 2 * qp + half;
            const float* v = half ? hi : lo;
            const float4 fq = *(const float4*)(g_Fq + ((size_t)(n * PP + q)) * UU + u0);
            const float msk = (em[q] != 0u) ? 1.0f : 0.0f;
            const float de = (q == p) ? 1.0f : 0.0f;
            float4 o;
            o.x = (v[0] + fq.x + fp4.x + de * fd4.x) * msk;
            o.y = (v[1] + fq.y + fp4.y + de * fd4.y) * msk;
            o.z = (v[2] + fq.z + fp4.z + de * fd4.z) * msk;
            o.w = (v[3] + fq.w + fp4.w + de * fd4.w) * msk;
            *(float4*)(out + (((size_t)(n * PP + p)) * PP + q) * UU + u0) = o;
        }
    }
}

// ---------------- launch ----------------
extern "C" void kernel_launch(void* const* d_in, const int* in_sizes, int n_in,
                              void* d_out, int out_size) {
    (void)in_sizes; (void)n_in; (void)out_size;
    const float*        x      = (const float*)d_in[0];
    const unsigned int* mask   = (const unsigned int*)d_in[1];
    const float*        npart  = (const float*)d_in[2];
    const float*        alpha0 = (const float*)d_in[3];
    const float*        c00    = (const float*)d_in[4];
    const float*        c01    = (const float*)d_in[5];
    const float*        c10    = (const float*)d_in[6];
    const float*        c11    = (const float*)d_in[7];
    const float*        bias   = (const float*)d_in[8];
    const float*        dbias  = (const float*)d_in[9];
    float* out = (float*)d_out;

    fuse_kernel<<<dim3(NPG, NN), 256>>>(x, npart);
    pro_kernel<<<dim3(32, NN), 256>>>(npart, alpha0, c00, c01, c10, c11, bias, dbias);

    cudaFuncSetAttribute(main_kernel, cudaFuncAttributeMaxDynamicSharedMemorySize,
                         SMEM_FLOATS * 4);
    main_kernel<<<dim3(PP, NN), 256, SMEM_FLOATS * 4>>>(x, mask, c00, c01, c10, c11, out);
}